// round 12
// baseline (speedup 1.0000x reference)
#include <cuda_runtime.h>
#include <cuda_fp16.h>
#include <cstdint>
#include <cstddef>

// Problem constants (fixed shapes from setup_inputs)
#define BATCH 2
#define SEQ   2048
#define CDIM  1024
#define NHEAD 16
#define HDIM  64
#define MROWS (BATCH * SEQ)          // 4096
#define QKVC  (3 * CDIM)             // 3072

// Scratch (allocation-free rule: __device__ globals)
__device__ __half g_qkv[(size_t)MROWS * QKVC];       // 24 MB fp16 qkv
__device__ __half g_x16[(size_t)MROWS * CDIM];       //  8 MB fp16 cast of x
__device__ __half g_qb[(size_t)MROWS * CDIM];        //  8 MB [b][h][t][d]
__device__ __half g_kb[(size_t)MROWS * CDIM];
__device__ __half g_vb[(size_t)MROWS * CDIM];
__device__ __half g_attn[(size_t)MROWS * CDIM];      //  8 MB attn output fp16
__device__ __half g_W1 [(size_t)QKVC * CDIM];        //  6 MB [N=3072][K=1024] Wqkv^T fp16
__device__ __half g_W2 [(size_t)CDIM * CDIM];        //  2 MB [N=1024][K=1024] Wout^T fp16

// ---------------------------------------------------------------------------
// Common PTX helpers
// ---------------------------------------------------------------------------
__device__ __forceinline__ uint32_t sw_off(int row, int col) {
    // XOR swizzle on 16B chunks within a 64-elt (128B) 16-bit row
    return (uint32_t)(row * 64 + ((((col >> 3) ^ (row & 7)) << 3) | (col & 7)));
}
__device__ __forceinline__ void ldm_x4(uint32_t& r0, uint32_t& r1,
                                       uint32_t& r2, uint32_t& r3, uint32_t a) {
    asm volatile("ldmatrix.sync.aligned.m8n8.x4.shared.b16 {%0,%1,%2,%3}, [%4];"
                 : "=r"(r0), "=r"(r1), "=r"(r2), "=r"(r3) : "r"(a));
}
__device__ __forceinline__ void ldm_x4_t(uint32_t& r0, uint32_t& r1,
                                         uint32_t& r2, uint32_t& r3, uint32_t a) {
    asm volatile("ldmatrix.sync.aligned.m8n8.x4.trans.shared.b16 {%0,%1,%2,%3}, [%4];"
                 : "=r"(r0), "=r"(r1), "=r"(r2), "=r"(r3) : "r"(a));
}
__device__ __forceinline__ void mma16816_f16(float* c, const uint32_t* a,
                                             uint32_t b0, uint32_t b1) {
    asm volatile(
        "mma.sync.aligned.m16n8k16.row.col.f32.f16.f16.f32 "
        "{%0,%1,%2,%3}, {%4,%5,%6,%7}, {%8,%9}, {%0,%1,%2,%3};"
        : "+f"(c[0]), "+f"(c[1]), "+f"(c[2]), "+f"(c[3])
        : "r"(a[0]), "r"(a[1]), "r"(a[2]), "r"(a[3]), "r"(b0), "r"(b1));
}
// fp16-accumulator MMA, fresh start (C = 0)
__device__ __forceinline__ void mma16816_h_zero(uint32_t* d, const uint32_t* a,
                                                uint32_t b0, uint32_t b1) {
    asm volatile(
        "mma.sync.aligned.m16n8k16.row.col.f16.f16.f16.f16 "
        "{%0,%1}, {%2,%3,%4,%5}, {%6,%7}, {%8,%8};"
        : "=r"(d[0]), "=r"(d[1])
        : "r"(a[0]), "r"(a[1]), "r"(a[2]), "r"(a[3]), "r"(b0), "r"(b1),
          "r"(0u));
}
// fp16-accumulator MMA, in-place accumulate
__device__ __forceinline__ void mma16816_h_acc(uint32_t* d, const uint32_t* a,
                                               uint32_t b0, uint32_t b1) {
    asm volatile(
        "mma.sync.aligned.m16n8k16.row.col.f16.f16.f16.f16 "
        "{%0,%1}, {%2,%3,%4,%5}, {%6,%7}, {%0,%1};"
        : "+r"(d[0]), "+r"(d[1])
        : "r"(a[0]), "r"(a[1]), "r"(a[2]), "r"(a[3]), "r"(b0), "r"(b1));
}
__device__ __forceinline__ float ex2f(float x) {
    float r;
    asm("ex2.approx.ftz.f32 %0, %1;" : "=f"(r) : "f"(x));
    return r;
}
__device__ __forceinline__ void cp16(uint32_t dst, const void* src) {
    asm volatile("cp.async.cg.shared.global [%0], [%1], 16;" :: "r"(dst), "l"(src));
}

// ---------------------------------------------------------------------------
// Fused prep: block ranges do (a) x -> fp16 cast, (b) Wqkv transpose+cast,
// (c) Wout transpose+cast. 256 threads flat.
// ---------------------------------------------------------------------------
__device__ __forceinline__ void trans_tile(const float* __restrict__ W,
                                           __half* __restrict__ Wt,
                                           int K, int N, int bx, int by,
                                           int tx, int ty, float (*s)[33])
{
    const int k0 = by * 32, n0 = bx * 32;
    #pragma unroll
    for (int i = 0; i < 4; ++i)
        s[ty + i * 8][tx] = W[(size_t)(k0 + ty + i * 8) * N + n0 + tx];
    __syncthreads();
    #pragma unroll
    for (int i = 0; i < 4; ++i) {
        const int n = n0 + ty + i * 8, k = k0 + tx;
        Wt[(size_t)n * K + k] = __float2half_rn(s[tx][ty + i * 8]);
    }
}

#define PREP_CAST_BLKS  (MROWS * CDIM / 2 / 256)          // 8192
#define PREP_W1_BLKS    ((QKVC / 32) * (CDIM / 32))       // 3072
#define PREP_W2_BLKS    ((CDIM / 32) * (CDIM / 32))       // 1024

__global__ void prep_kernel(const float* __restrict__ x, __half* __restrict__ x16,
                            const float* __restrict__ Wqkv, __half* __restrict__ W1,
                            const float* __restrict__ Wout, __half* __restrict__ W2)
{
    __shared__ float s[32][33];
    const int bid = blockIdx.x;
    const int tid = threadIdx.x;
    if (bid < PREP_CAST_BLKS) {
        const int idx = bid * 256 + tid;
        const float2 v = *(const float2*)(x + (size_t)idx * 2);
        __half2 hh;
        hh.x = __float2half_rn(v.x);
        hh.y = __float2half_rn(v.y);
        *(__half2*)(x16 + (size_t)idx * 2) = hh;
    } else if (bid < PREP_CAST_BLKS + PREP_W1_BLKS) {
        const int j = bid - PREP_CAST_BLKS;
        trans_tile(Wqkv, W1, CDIM, QKVC, j % (QKVC / 32), j / (QKVC / 32),
                   tid & 31, tid >> 5, s);
    } else {
        const int j = bid - PREP_CAST_BLKS - PREP_W1_BLKS;
        trans_tile(Wout, W2, CDIM, CDIM, j % (CDIM / 32), j / (CDIM / 32),
                   tid & 31, tid >> 5, s);
    }
}

// ---------------------------------------------------------------------------
// GEMM1: fp16 in/out, 128x64 tiles, 128 threads (4 warps, 2M x 2N, warp 64x32).
// EXPERIMENT: fp16-accumulator MMAs chained over 32-K, promoted to fp32 every
// 2 MMAs (tests the "fp32-acc HMMA is half-rate" hypothesis).
// 3-stage cp.async pipeline.
// ---------------------------------------------------------------------------
#define GM_BK 64
#define G1_NSTG 3
#define G1_STG_BYTES 24576   // 16 KB A + 8 KB B

extern __shared__ __half smem_dyn[];

__global__ __launch_bounds__(128, 3) void hgemm_n64_kernel(
    const __half* __restrict__ A,   // [M][K]
    const __half* __restrict__ Bt,  // [N][K]
    const float* __restrict__ bias, __half* __restrict__ C,
    int M, int N, int K)
{
    const int tid = threadIdx.x, lane = tid & 31, wid = tid >> 5;
    const int m0 = blockIdx.y * 128, n0 = blockIdx.x * 64;
    const int wm = (wid >> 1) * 64, wn = (wid & 1) * 32;
    const int lrow = lane & 15, lcol8 = (lane >> 4) * 8;

    const uint32_t sBase = (uint32_t)__cvta_generic_to_shared(smem_dyn);

    const __half* Ag = A  + (size_t)m0 * K;
    const __half* Bg = Bt + (size_t)n0 * K;

    auto loadTile = [&](int it, int stg) {
        const __half* ag = Ag + it * GM_BK;
        const __half* bg = Bg + it * GM_BK;
        const uint32_t sa = sBase + stg * G1_STG_BYTES;
        const uint32_t sb = sa + 16384;
        #pragma unroll
        for (int e = tid; e < 1024; e += 128) {         // A: 128 rows x 8 chunks
            const int row = e >> 3, ch = e & 7;
            cp16(sa + 2 * sw_off(row, ch * 8), ag + (size_t)row * K + ch * 8);
        }
        #pragma unroll
        for (int e = tid; e < 512; e += 128) {          // B: 64 rows x 8 chunks
            const int row = e >> 3, ch = e & 7;
            cp16(sb + 2 * sw_off(row, ch * 8), bg + (size_t)row * K + ch * 8);
        }
        asm volatile("cp.async.commit_group;" ::: "memory");
    };

    float acc[4][4][4];
    #pragma unroll
    for (int mt = 0; mt < 4; ++mt)
        #pragma unroll
        for (int nb = 0; nb < 4; ++nb)
            #pragma unroll
            for (int r = 0; r < 4; ++r) acc[mt][nb][r] = 0.f;

    uint32_t facc[4][4][2];   // fp16x2 partial accumulators (32-K chains)

    const int kIters = K / GM_BK;
    loadTile(0, 0);
    loadTile(1, 1);

    for (int it = 0; it < kIters; ++it) {
        asm volatile("cp.async.wait_group 1;" ::: "memory");
        __syncthreads();

        if (it + 2 < kIters) loadTile(it + 2, (it + 2) % G1_NSTG);
        else asm volatile("cp.async.commit_group;" ::: "memory");

        const uint32_t sa = sBase + (it % G1_NSTG) * G1_STG_BYTES;
        const uint32_t sb = sa + 16384;

        #pragma unroll
        for (int k16 = 0; k16 < 4; ++k16) {
            uint32_t af[4][4];
            #pragma unroll
            for (int mt = 0; mt < 4; ++mt)
                ldm_x4(af[mt][0], af[mt][1], af[mt][2], af[mt][3],
                       sa + 2 * sw_off(wm + mt * 16 + lrow, k16 * 16 + lcol8));
            uint32_t bfr[4][2];
            #pragma unroll
            for (int nt = 0; nt < 2; ++nt) {
                uint32_t r0, r1, r2, r3;
                ldm_x4(r0, r1, r2, r3,
                       sb + 2 * sw_off(wn + nt * 16 + lrow, k16 * 16 + lcol8));
                bfr[2 * nt][0] = r0; bfr[2 * nt][1] = r2;
                bfr[2 * nt + 1][0] = r1; bfr[2 * nt + 1][1] = r3;
            }
            if ((k16 & 1) == 0) {
                // fresh fp16 chain
                #pragma unroll
                for (int mt = 0; mt < 4; ++mt)
                    #pragma unroll
                    for (int nb = 0; nb < 4; ++nb)
                        mma16816_h_zero(facc[mt][nb], af[mt],
                                        bfr[nb][0], bfr[nb][1]);
            } else {
                // accumulate then promote to fp32
                #pragma unroll
                for (int mt = 0; mt < 4; ++mt)
                    #pragma unroll
                    for (int nb = 0; nb < 4; ++nb)
                        mma16816_h_acc(facc[mt][nb], af[mt],
                                       bfr[nb][0], bfr[nb][1]);
                #pragma unroll
                for (int mt = 0; mt < 4; ++mt)
                    #pragma unroll
                    for (int nb = 0; nb < 4; ++nb) {
                        const float2 lo = __half22float2(
                            *(const __half2*)&facc[mt][nb][0]);
                        const float2 hi = __half22float2(
                            *(const __half2*)&facc[mt][nb][1]);
                        acc[mt][nb][0] += lo.x;
                        acc[mt][nb][1] += lo.y;
                        acc[mt][nb][2] += hi.x;
                        acc[mt][nb][3] += hi.y;
                    }
            }
        }
    }

    #pragma unroll
    for (int mt = 0; mt < 4; ++mt) {
        const int r0 = m0 + wm + mt * 16 + (lane >> 2);
        #pragma unroll
        for (int nb = 0; nb < 4; ++nb) {
            const int cidx = n0 + wn + nb * 8 + (lane & 3) * 2;
            const float b0 = bias[cidx], b1 = bias[cidx + 1];
            *(__half2*)(C + (size_t)r0 * N + cidx) =
                __floats2half2_rn(acc[mt][nb][0] + b0, acc[mt][nb][1] + b1);
            *(__half2*)(C + (size_t)(r0 + 8) * N + cidx) =
                __floats2half2_rn(acc[mt][nb][2] + b0, acc[mt][nb][3] + b1);
        }
    }
}

// ---------------------------------------------------------------------------
// GEMM2: fp16 in, fp32 out, 128x128x64, 3-stage, 256 threads. (unchanged)
// ---------------------------------------------------------------------------
#define GM_NSTG 3
#define GM_STG_BYTES 32768   // 16KB A + 16KB B

__global__ __launch_bounds__(256) void hgemm_bias_kernel(
    const __half* __restrict__ A,   // [M][K]
    const __half* __restrict__ Bt,  // [N][K]
    const float* __restrict__ bias, float* __restrict__ C,
    int M, int N, int K)
{
    const int tid = threadIdx.x, lane = tid & 31, wid = tid >> 5;
    const int m0 = blockIdx.y * 128, n0 = blockIdx.x * 128;
    const int wm = (wid >> 2) * 64, wn = (wid & 3) * 32;
    const int lrow = lane & 15, lcol8 = (lane >> 4) * 8;

    const uint32_t sBase = (uint32_t)__cvta_generic_to_shared(smem_dyn);

    const __half* Ag = A  + (size_t)m0 * K;
    const __half* Bg = Bt + (size_t)n0 * K;

    auto loadTile = [&](int it, int stg) {
        const __half* ag = Ag + it * GM_BK;
        const __half* bg = Bg + it * GM_BK;
        const uint32_t sa = sBase + stg * GM_STG_BYTES;
        const uint32_t sb = sa + 16384;
        #pragma unroll
        for (int e = tid; e < 1024; e += 256) {
            const int row = e >> 3, ch = e & 7;
            const uint32_t so = 2 * sw_off(row, ch * 8);
            cp16(sa + so, ag + (size_t)row * K + ch * 8);
            cp16(sb + so, bg + (size_t)row * K + ch * 8);
        }
        asm volatile("cp.async.commit_group;" ::: "memory");
    };

    float acc[4][4][4];
    #pragma unroll
    for (int mt = 0; mt < 4; ++mt)
        #pragma unroll
        for (int nb = 0; nb < 4; ++nb)
            #pragma unroll
            for (int r = 0; r < 4; ++r) acc[mt][nb][r] = 0.f;

    const int kIters = K / GM_BK;
    loadTile(0, 0);
    loadTile(1, 1);

    for (int it = 0; it < kIters; ++it) {
        asm volatile("cp.async.wait_group 1;" ::: "memory");
        __syncthreads();

        if (it + 2 < kIters) loadTile(it + 2, (it + 2) % GM_NSTG);
        else asm volatile("cp.async.commit_group;" ::: "memory");

        const uint32_t sa = sBase + (it % GM_NSTG) * GM_STG_BYTES;
        const uint32_t sb = sa + 16384;

        #pragma unroll
        for (int k16 = 0; k16 < 4; ++k16) {
            uint32_t af[4][4];
            #pragma unroll
            for (int mt = 0; mt < 4; ++mt)
                ldm_x4(af[mt][0], af[mt][1], af[mt][2], af[mt][3],
                       sa + 2 * sw_off(wm + mt * 16 + lrow, k16 * 16 + lcol8));
            uint32_t bfr[4][2];
            #pragma unroll
            for (int nt = 0; nt < 2; ++nt) {
                uint32_t r0, r1, r2, r3;
                ldm_x4(r0, r1, r2, r3,
                       sb + 2 * sw_off(wn + nt * 16 + lrow, k16 * 16 + lcol8));
                bfr[2 * nt][0] = r0; bfr[2 * nt][1] = r2;
                bfr[2 * nt + 1][0] = r1; bfr[2 * nt + 1][1] = r3;
            }
            #pragma unroll
            for (int mt = 0; mt < 4; ++mt)
                #pragma unroll
                for (int nb = 0; nb < 4; ++nb)
                    mma16816_f16(acc[mt][nb], af[mt], bfr[nb][0], bfr[nb][1]);
        }
    }

    #pragma unroll
    for (int mt = 0; mt < 4; ++mt) {
        const int r0 = m0 + wm + mt * 16 + (lane >> 2);
        #pragma unroll
        for (int nb = 0; nb < 4; ++nb) {
            const int cidx = n0 + wn + nb * 8 + (lane & 3) * 2;
            const float b0 = bias[cidx], b1 = bias[cidx + 1];
            *(float2*)(C + (size_t)r0 * N + cidx) =
                make_float2(acc[mt][nb][0] + b0, acc[mt][nb][1] + b1);
            *(float2*)(C + (size_t)(r0 + 8) * N + cidx) =
                make_float2(acc[mt][nb][2] + b0, acc[mt][nb][3] + b1);
        }
    }
}

// ---------------------------------------------------------------------------
// RoPE + fp16 relayout into [b][h][t][d]; reads fp16 qkv. (unchanged)
// ---------------------------------------------------------------------------
__global__ void rope_cast_kernel(const __half* __restrict__ qkv,
                                 __half* __restrict__ qb,
                                 __half* __restrict__ kb,
                                 __half* __restrict__ vb)
{
    const int total = MROWS * NHEAD * 32;
    int idx = blockIdx.x * blockDim.x + threadIdx.x;
    if (idx >= total) return;
    const int d = idx & 31;
    const int h = (idx >> 5) & (NHEAD - 1);
    const int m = idx >> 9;
    const int t = m & (SEQ - 1);
    const int b = m >> 11;

    const float inv_freq = exp2f((float)d * (-13.2877123795494493f / 32.0f));
    const float ang = (float)t * inv_freq;
    float s, c;
    sincosf(ang, &s, &c);

    const float QS = 0.125f * 1.4426950408889634f;  // 1/sqrt(64) * log2(e)

    const __half* base = qkv + (size_t)m * QKVC + h * HDIM + d;
    const float q1 = __half2float(base[0]);
    const float q2 = __half2float(base[32]);
    const float k1 = __half2float(base[CDIM]);
    const float k2 = __half2float(base[CDIM + 32]);

    const size_t ob = ((size_t)(b * NHEAD + h) * SEQ + t) * HDIM + d;
    qb[ob]      = __float2half((q1 * c - q2 * s) * QS);
    qb[ob + 32] = __float2half((q2 * c + q1 * s) * QS);
    kb[ob]      = __float2half(k1 * c - k2 * s);
    kb[ob + 32] = __float2half(k2 * c + k1 * s);
    vb[ob]      = base[2 * CDIM];
    vb[ob + 32] = base[2 * CDIM + 32];
}

// ---------------------------------------------------------------------------
// fp16 flash attention (unchanged from R11).
// ---------------------------------------------------------------------------
#define FA_BM 128
#define FA_BN 64
#define FA_TILES (SEQ / FA_BN)   // 32

__global__ __launch_bounds__(256) void fa_kernel(
    const __half* __restrict__ Q, const __half* __restrict__ K,
    const __half* __restrict__ V, __half* __restrict__ attn)
{
    const int bh = blockIdx.y;
    const int b  = bh >> 4;
    const int h  = bh & 15;
    const int q0 = blockIdx.x * FA_BM;
    const int tid  = threadIdx.x;
    const int lane = tid & 31;
    const int wid  = tid >> 5;

    __shared__ __half sQ[FA_BM * HDIM];
    __shared__ __half sK[2][FA_BN * HDIM];
    __shared__ __half sV[2][FA_BN * HDIM];

    const __half* qg = Q + ((size_t)bh * SEQ + q0) * HDIM;
    const __half* kg = K + (size_t)bh * SEQ * HDIM;
    const __half* vg = V + (size_t)bh * SEQ * HDIM;

    const uint32_t sQb  = (uint32_t)__cvta_generic_to_shared(sQ);
    const uint32_t sKb0 = (uint32_t)__cvta_generic_to_shared(sK[0]);
    const uint32_t sKb1 = (uint32_t)__cvta_generic_to_shared(sK[1]);
    const uint32_t sVb0 = (uint32_t)__cvta_generic_to_shared(sV[0]);
    const uint32_t sVb1 = (uint32_t)__cvta_generic_to_shared(sV[1]);

    #pragma unroll
    for (int e = tid; e < FA_BM * 8; e += 256) {
        const int row = e >> 3, ch = e & 7;
        *(uint4*)&sQ[sw_off(row, ch * 8)] = *(const uint4*)(qg + row * 64 + ch * 8);
    }

    #pragma unroll
    for (int pt = 0; pt < 2; ++pt) {
        const __half* kt = kg + pt * FA_BN * HDIM;
        const __half* vt = vg + pt * FA_BN * HDIM;
        const uint32_t kb = pt ? sKb1 : sKb0;
        const uint32_t vb = pt ? sVb1 : sVb0;
        #pragma unroll
        for (int e = tid; e < FA_BN * 8; e += 256) {
            const int row = e >> 3, ch = e & 7;
            const uint32_t so = 2 * sw_off(row, ch * 8);
            cp16(kb + so, kt + row * 64 + ch * 8);
            cp16(vb + so, vt + row * 64 + ch * 8);
        }
        asm volatile("cp.async.commit_group;" ::: "memory");
    }

    __syncthreads();

    uint32_t aq[4][4];
    {
        const int qr = wid * 16 + (lane & 15);
        const int qc = (lane >> 4) * 8;
        #pragma unroll
        for (int c4 = 0; c4 < 4; ++c4)
            ldm_x4(aq[c4][0], aq[c4][1], aq[c4][2], aq[c4][3],
                   sQb + 2 * sw_off(qr, c4 * 16 + qc));
    }

    float o[8][4];
    #pragma unroll
    for (int j = 0; j < 8; ++j)
        #pragma unroll
        for (int r = 0; r < 4; ++r) o[j][r] = 0.f;
    float m0 = -1e30f, m1 = -1e30f, l0 = 0.f, l1 = 0.f;

    const int lrow = lane & 15;
    const int lcol8 = (lane >> 4) * 8;

    for (int t = 0; t < FA_TILES; ++t) {
        if (t < FA_TILES - 1)
            asm volatile("cp.async.wait_group 1;" ::: "memory");
        else
            asm volatile("cp.async.wait_group 0;" ::: "memory");
        __syncthreads();

        const uint32_t kb = (t & 1) ? sKb1 : sKb0;
        const uint32_t vb = (t & 1) ? sVb1 : sVb0;

        float c[8][4];
        #pragma unroll
        for (int j = 0; j < 8; ++j)
            #pragma unroll
            for (int r = 0; r < 4; ++r) c[j][r] = 0.f;

        #pragma unroll
        for (int n16 = 0; n16 < 4; ++n16) {
            #pragma unroll
            for (int dc = 0; dc < 4; ++dc) {
                uint32_t r0, r1, r2, r3;
                ldm_x4(r0, r1, r2, r3,
                       kb + 2 * sw_off(n16 * 16 + lrow, dc * 16 + lcol8));
                mma16816_f16(c[2 * n16 + 0], aq[dc], r0, r2);
                mma16816_f16(c[2 * n16 + 1], aq[dc], r1, r3);
            }
        }

        float t0 = -1e30f, t1 = -1e30f;
        #pragma unroll
        for (int j = 0; j < 8; ++j) {
            t0 = fmaxf(t0, fmaxf(c[j][0], c[j][1]));
            t1 = fmaxf(t1, fmaxf(c[j][2], c[j][3]));
        }
        t0 = fmaxf(t0, __shfl_xor_sync(0xffffffffu, t0, 1));
        t0 = fmaxf(t0, __shfl_xor_sync(0xffffffffu, t0, 2));
        t1 = fmaxf(t1, __shfl_xor_sync(0xffffffffu, t1, 1));
        t1 = fmaxf(t1, __shfl_xor_sync(0xffffffffu, t1, 2));

        const float m0n = fmaxf(m0, t0);
        const float m1n = fmaxf(m1, t1);
        const float a0 = ex2f(m0 - m0n);
        const float a1 = ex2f(m1 - m1n);
        m0 = m0n; m1 = m1n;

        #pragma unroll
        for (int j = 0; j < 8; ++j) {
            o[j][0] *= a0; o[j][1] *= a0;
            o[j][2] *= a1; o[j][3] *= a1;
        }

        float s0 = 0.f, s1 = 0.f;
        #pragma unroll
        for (int kc = 0; kc < 4; ++kc) {
            uint32_t ap[4];
            #pragma unroll
            for (int jj = 0; jj < 2; ++jj) {
                const int j = 2 * kc + jj;
                const float p0 = ex2f(c[j][0] - m0);
                const float p1 = ex2f(c[j][1] - m0);
                const float p2 = ex2f(c[j][2] - m1);
                const float p3 = ex2f(c[j][3] - m1);
                s0 += p0 + p1;
                s1 += p2 + p3;
                __half2 u = __floats2half2_rn(p0, p1);
                __half2 w = __floats2half2_rn(p2, p3);
                ap[2 * jj + 0] = *(uint32_t*)&u;
                ap[2 * jj + 1] = *(uint32_t*)&w;
            }
            #pragma unroll
            for (int dc = 0; dc < 4; ++dc) {
                uint32_t r0, r1, r2, r3;
                ldm_x4_t(r0, r1, r2, r3,
                         vb + 2 * sw_off(kc * 16 + lrow, dc * 16 + lcol8));
                mma16816_f16(o[2 * dc + 0], ap, r0, r1);
                mma16816_f16(o[2 * dc + 1], ap, r2, r3);
            }
        }

        s0 += __shfl_xor_sync(0xffffffffu, s0, 1);
        s0 += __shfl_xor_sync(0xffffffffu, s0, 2);
        s1 += __shfl_xor_sync(0xffffffffu, s1, 1);
        s1 += __shfl_xor_sync(0xffffffffu, s1, 2);
        l0 = l0 * a0 + s0;
        l1 = l1 * a1 + s1;

        __syncthreads();

        if (t + 2 < FA_TILES) {
            const __half* kt = kg + (t + 2) * FA_BN * HDIM;
            const __half* vt = vg + (t + 2) * FA_BN * HDIM;
            const uint32_t kbn = (t & 1) ? sKb1 : sKb0;
            const uint32_t vbn = (t & 1) ? sVb1 : sVb0;
            #pragma unroll
            for (int e = tid; e < FA_BN * 8; e += 256) {
                const int row = e >> 3, ch = e & 7;
                const uint32_t so = 2 * sw_off(row, ch * 8);
                cp16(kbn + so, kt + row * 64 + ch * 8);
                cp16(vbn + so, vt + row * 64 + ch * 8);
            }
        }
        asm volatile("cp.async.commit_group;" ::: "memory");
    }

    const float inv0 = 1.0f / l0;
    const float inv1 = 1.0f / l1;
    const int g = lane >> 2;
    const int cq = (lane & 3) * 2;
    const int row0 = q0 + wid * 16 + g;
    const int row1 = row0 + 8;
    __half* ab0 = attn + (size_t)(b * SEQ + row0) * CDIM + h * HDIM + cq;
    __half* ab1 = attn + (size_t)(b * SEQ + row1) * CDIM + h * HDIM + cq;
    #pragma unroll
    for (int j = 0; j < 8; ++j) {
        *(__half2*)(ab0 + j * 8) = __floats2half2_rn(o[j][0] * inv0, o[j][1] * inv0);
        *(__half2*)(ab1 + j * 8) = __floats2half2_rn(o[j][2] * inv1, o[j][3] * inv1);
    }
}

// ---------------------------------------------------------------------------
// Launch
// ---------------------------------------------------------------------------
extern "C" void kernel_launch(void* const* d_in, const int* in_sizes, int n_in,
                              void* d_out, int out_size)
{
    const float* x    = (const float*)d_in[0];
    const float* Wqkv = (const float*)d_in[1];
    const float* bqkv = (const float*)d_in[2];
    const float* Wout = (const float*)d_in[3];
    const float* bout = (const float*)d_in[4];
    float* out = (float*)d_out;

    __half *qkv = nullptr, *x16 = nullptr, *qb = nullptr, *kb = nullptr, *vb = nullptr;
    __half *attn = nullptr, *W1 = nullptr, *W2 = nullptr;
    cudaGetSymbolAddress((void**)&qkv, g_qkv);
    cudaGetSymbolAddress((void**)&x16, g_x16);
    cudaGetSymbolAddress((void**)&qb, g_qb);
    cudaGetSymbolAddress((void**)&kb, g_kb);
    cudaGetSymbolAddress((void**)&vb, g_vb);
    cudaGetSymbolAddress((void**)&attn, g_attn);
    cudaGetSymbolAddress((void**)&W1,  g_W1);
    cudaGetSymbolAddress((void**)&W2,  g_W2);

    const int G1_SMEM = G1_NSTG * G1_STG_BYTES;     // 73728
    const int G2_SMEM = GM_NSTG * GM_STG_BYTES;     // 98304
    cudaFuncSetAttribute(hgemm_n64_kernel,
                         cudaFuncAttributeMaxDynamicSharedMemorySize, G1_SMEM);
    cudaFuncSetAttribute(hgemm_bias_kernel,
                         cudaFuncAttributeMaxDynamicSharedMemorySize, G2_SMEM);

    // 1) fused prep: cast x -> x16, transpose Wqkv -> W1, Wout -> W2
    prep_kernel<<<PREP_CAST_BLKS + PREP_W1_BLKS + PREP_W2_BLKS, 256>>>(
        x, x16, Wqkv, W1, Wout, W2);

    // 2) qkv = x @ Wqkv + bqkv   (fp16-accumulator experiment)
    hgemm_n64_kernel<<<dim3(QKVC / 64, MROWS / 128), 128, G1_SMEM>>>(
        x16, W1, bqkv, qkv, MROWS, QKVC, CDIM);

    // 3) RoPE + [b,h,t,d] relayout
    {
        const int total = MROWS * NHEAD * 32;
        rope_cast_kernel<<<(total + 255) / 256, 256>>>(qkv, qb, kb, vb);
    }

    // 4) flash attention -> attn fp16
    fa_kernel<<<dim3(SEQ / FA_BM, BATCH * NHEAD), 256>>>(qb, kb, vb, attn);

    // 5) out = attn @ Wout + bout
    hgemm_bias_kernel<<<dim3(CDIM / 128, MROWS / 128), 256, G2_SMEM>>>(
        attn, W2, bout, out, MROWS, CDIM, CDIM);
}

// round 13
// speedup vs baseline: 1.0987x; 1.0987x over previous
#include <cuda_runtime.h>
#include <cuda_fp16.h>
#include <cstdint>
#include <cstddef>

// Problem constants (fixed shapes from setup_inputs)
#define BATCH 2
#define SEQ   2048
#define CDIM  1024
#define NHEAD 16
#define HDIM  64
#define MROWS (BATCH * SEQ)          // 4096
#define QKVC  (3 * CDIM)             // 3072

// Scratch (allocation-free rule: __device__ globals)
__device__ __half g_x16[(size_t)MROWS * CDIM];       //  8 MB fp16 cast of x
__device__ __half g_qb[(size_t)MROWS * CDIM];        //  8 MB [b][h][t][d]
__device__ __half g_kb[(size_t)MROWS * CDIM];
__device__ __half g_vb[(size_t)MROWS * CDIM];
__device__ __half g_attn[(size_t)MROWS * CDIM];      //  8 MB attn output fp16
__device__ __half g_W1 [(size_t)QKVC * CDIM];        //  6 MB [N=3072][K=1024] Wqkv^T fp16
__device__ __half g_W2 [(size_t)CDIM * CDIM];        //  2 MB [N=1024][K=1024] Wout^T fp16

// ---------------------------------------------------------------------------
// Common PTX helpers
// ---------------------------------------------------------------------------
__device__ __forceinline__ uint32_t sw_off(int row, int col) {
    // XOR swizzle on 16B chunks within a 64-elt (128B) 16-bit row
    return (uint32_t)(row * 64 + ((((col >> 3) ^ (row & 7)) << 3) | (col & 7)));
}
__device__ __forceinline__ void ldm_x4(uint32_t& r0, uint32_t& r1,
                                       uint32_t& r2, uint32_t& r3, uint32_t a) {
    asm volatile("ldmatrix.sync.aligned.m8n8.x4.shared.b16 {%0,%1,%2,%3}, [%4];"
                 : "=r"(r0), "=r"(r1), "=r"(r2), "=r"(r3) : "r"(a));
}
__device__ __forceinline__ void ldm_x4_t(uint32_t& r0, uint32_t& r1,
                                         uint32_t& r2, uint32_t& r3, uint32_t a) {
    asm volatile("ldmatrix.sync.aligned.m8n8.x4.trans.shared.b16 {%0,%1,%2,%3}, [%4];"
                 : "=r"(r0), "=r"(r1), "=r"(r2), "=r"(r3) : "r"(a));
}
__device__ __forceinline__ void mma16816_f16(float* c, const uint32_t* a,
                                             uint32_t b0, uint32_t b1) {
    asm volatile(
        "mma.sync.aligned.m16n8k16.row.col.f32.f16.f16.f32 "
        "{%0,%1,%2,%3}, {%4,%5,%6,%7}, {%8,%9}, {%0,%1,%2,%3};"
        : "+f"(c[0]), "+f"(c[1]), "+f"(c[2]), "+f"(c[3])
        : "r"(a[0]), "r"(a[1]), "r"(a[2]), "r"(a[3]), "r"(b0), "r"(b1));
}
__device__ __forceinline__ float ex2f(float x) {
    float r;
    asm("ex2.approx.ftz.f32 %0, %1;" : "=f"(r) : "f"(x));
    return r;
}
__device__ __forceinline__ void cp16(uint32_t dst, const void* src) {
    asm volatile("cp.async.cg.shared.global [%0], [%1], 16;" :: "r"(dst), "l"(src));
}

// ---------------------------------------------------------------------------
// Fused prep: (a) x -> fp16 cast, (b) Wqkv transpose+cast, (c) Wout
// transpose+cast. 256 threads flat.
// ---------------------------------------------------------------------------
__device__ __forceinline__ void trans_tile(const float* __restrict__ W,
                                           __half* __restrict__ Wt,
                                           int K, int N, int bx, int by,
                                           int tx, int ty, float (*s)[33])
{
    const int k0 = by * 32, n0 = bx * 32;
    #pragma unroll
    for (int i = 0; i < 4; ++i)
        s[ty + i * 8][tx] = W[(size_t)(k0 + ty + i * 8) * N + n0 + tx];
    __syncthreads();
    #pragma unroll
    for (int i = 0; i < 4; ++i) {
        const int n = n0 + ty + i * 8, k = k0 + tx;
        Wt[(size_t)n * K + k] = __float2half_rn(s[tx][ty + i * 8]);
    }
}

#define PREP_CAST_BLKS  (MROWS * CDIM / 2 / 256)          // 8192
#define PREP_W1_BLKS    ((QKVC / 32) * (CDIM / 32))       // 3072
#define PREP_W2_BLKS    ((CDIM / 32) * (CDIM / 32))       // 1024

__global__ void prep_kernel(const float* __restrict__ x, __half* __restrict__ x16,
                            const float* __restrict__ Wqkv, __half* __restrict__ W1,
                            const float* __restrict__ Wout, __half* __restrict__ W2)
{
    __shared__ float s[32][33];
    const int bid = blockIdx.x;
    const int tid = threadIdx.x;
    if (bid < PREP_CAST_BLKS) {
        const int idx = bid * 256 + tid;
        const float2 v = *(const float2*)(x + (size_t)idx * 2);
        __half2 hh;
        hh.x = __float2half_rn(v.x);
        hh.y = __float2half_rn(v.y);
        *(__half2*)(x16 + (size_t)idx * 2) = hh;
    } else if (bid < PREP_CAST_BLKS + PREP_W1_BLKS) {
        const int j = bid - PREP_CAST_BLKS;
        trans_tile(Wqkv, W1, CDIM, QKVC, j % (QKVC / 32), j / (QKVC / 32),
                   tid & 31, tid >> 5, s);
    } else {
        const int j = bid - PREP_CAST_BLKS - PREP_W1_BLKS;
        trans_tile(Wout, W2, CDIM, CDIM, j % (CDIM / 32), j / (CDIM / 32),
                   tid & 31, tid >> 5, s);
    }
}

// ---------------------------------------------------------------------------
// GEMM1 + fused RoPE epilogue.
// fp16 in, 128x64 tiles, 128 threads (4 warps, 2M x 2N, warp 64x32),
// 3-stage cp.async pipeline + register double-buffered fragments (R11 cfg).
// N-tile 64 == one head-slice of q, k, or v:
//   sec = n0>>10 (0=q,1=k,2=v), h = (n0&1023)>>6.
// v: direct fp16 store to vb[b,h,t,d].
// q/k: stage fp32 acc+bias in smem, apply RoPE (fp32), store fp16.
// ---------------------------------------------------------------------------
#define GM_BK 64
#define G1_NSTG 3
#define G1_STG_BYTES 24576   // 16 KB A + 8 KB B

extern __shared__ __half smem_dyn[];

__global__ __launch_bounds__(128, 3) void hgemm_rope_kernel(
    const __half* __restrict__ A,   // [M][K] = x16
    const __half* __restrict__ Bt,  // [N][K] = W1
    const float* __restrict__ bias, // bqkv
    __half* __restrict__ qb, __half* __restrict__ kb, __half* __restrict__ vb,
    int M, int N, int K)
{
    const int tid = threadIdx.x, lane = tid & 31, wid = tid >> 5;
    const int m0 = blockIdx.y * 128, n0 = blockIdx.x * 64;
    const int wm = (wid >> 1) * 64, wn = (wid & 1) * 32;
    const int lrow = lane & 15, lcol8 = (lane >> 4) * 8;

    const uint32_t sBase = (uint32_t)__cvta_generic_to_shared(smem_dyn);

    const __half* Ag = A  + (size_t)m0 * K;
    const __half* Bg = Bt + (size_t)n0 * K;

    auto loadTile = [&](int it, int stg) {
        const __half* ag = Ag + it * GM_BK;
        const __half* bg = Bg + it * GM_BK;
        const uint32_t sa = sBase + stg * G1_STG_BYTES;
        const uint32_t sb = sa + 16384;
        #pragma unroll
        for (int e = tid; e < 1024; e += 128) {         // A: 128 rows x 8 chunks
            const int row = e >> 3, ch = e & 7;
            cp16(sa + 2 * sw_off(row, ch * 8), ag + (size_t)row * K + ch * 8);
        }
        #pragma unroll
        for (int e = tid; e < 512; e += 128) {          // B: 64 rows x 8 chunks
            const int row = e >> 3, ch = e & 7;
            cp16(sb + 2 * sw_off(row, ch * 8), bg + (size_t)row * K + ch * 8);
        }
        asm volatile("cp.async.commit_group;" ::: "memory");
    };

    float acc[4][4][4];
    #pragma unroll
    for (int mt = 0; mt < 4; ++mt)
        #pragma unroll
        for (int nb = 0; nb < 4; ++nb)
            #pragma unroll
            for (int r = 0; r < 4; ++r) acc[mt][nb][r] = 0.f;

    const int kIters = K / GM_BK;
    loadTile(0, 0);
    loadTile(1, 1);

    uint32_t af[2][4][4];
    uint32_t bf[2][4][2];

    for (int it = 0; it < kIters; ++it) {
        asm volatile("cp.async.wait_group 1;" ::: "memory");
        __syncthreads();

        if (it + 2 < kIters) loadTile(it + 2, (it + 2) % G1_NSTG);
        else asm volatile("cp.async.commit_group;" ::: "memory");

        const uint32_t sa = sBase + (it % G1_NSTG) * G1_STG_BYTES;
        const uint32_t sb = sa + 16384;

        #pragma unroll
        for (int mt = 0; mt < 4; ++mt)
            ldm_x4(af[0][mt][0], af[0][mt][1], af[0][mt][2], af[0][mt][3],
                   sa + 2 * sw_off(wm + mt * 16 + lrow, lcol8));
        #pragma unroll
        for (int nt = 0; nt < 2; ++nt) {
            uint32_t r0, r1, r2, r3;
            ldm_x4(r0, r1, r2, r3, sb + 2 * sw_off(wn + nt * 16 + lrow, lcol8));
            bf[0][2 * nt][0] = r0;     bf[0][2 * nt][1] = r2;
            bf[0][2 * nt + 1][0] = r1; bf[0][2 * nt + 1][1] = r3;
        }

        #pragma unroll
        for (int k16 = 0; k16 < 4; ++k16) {
            const int cur = k16 & 1, nxt = cur ^ 1;
            if (k16 < 3) {
                #pragma unroll
                for (int mt = 0; mt < 4; ++mt)
                    ldm_x4(af[nxt][mt][0], af[nxt][mt][1],
                           af[nxt][mt][2], af[nxt][mt][3],
                           sa + 2 * sw_off(wm + mt * 16 + lrow,
                                           (k16 + 1) * 16 + lcol8));
                #pragma unroll
                for (int nt = 0; nt < 2; ++nt) {
                    uint32_t r0, r1, r2, r3;
                    ldm_x4(r0, r1, r2, r3,
                           sb + 2 * sw_off(wn + nt * 16 + lrow,
                                           (k16 + 1) * 16 + lcol8));
                    bf[nxt][2 * nt][0] = r0;     bf[nxt][2 * nt][1] = r2;
                    bf[nxt][2 * nt + 1][0] = r1; bf[nxt][2 * nt + 1][1] = r3;
                }
            }
            #pragma unroll
            for (int mt = 0; mt < 4; ++mt)
                #pragma unroll
                for (int nb = 0; nb < 4; ++nb)
                    mma16816_f16(acc[mt][nb], af[cur][mt],
                                 bf[cur][nb][0], bf[cur][nb][1]);
        }
    }

    // ---- fused epilogue ----
    const int sec = n0 >> 10;               // 0=q, 1=k, 2=v
    const int h   = (n0 & 1023) >> 6;
    const int b   = m0 >> 11;
    const int t0  = m0 & (SEQ - 1);
    __half* outbase = (sec == 0 ? qb : (sec == 1 ? kb : vb))
                      + ((size_t)(b * NHEAD + h) * SEQ + t0) * HDIM;

    if (sec == 2) {
        // v: direct fp16 store (bias added), relayout to [b,h,t,d]
        #pragma unroll
        for (int mt = 0; mt < 4; ++mt) {
            const int r0 = wm + mt * 16 + (lane >> 2);
            #pragma unroll
            for (int nb = 0; nb < 4; ++nb) {
                const int cidx = wn + nb * 8 + (lane & 3) * 2;
                const float b0 = bias[n0 + cidx], b1 = bias[n0 + cidx + 1];
                *(__half2*)(outbase + (size_t)r0 * HDIM + cidx) =
                    __floats2half2_rn(acc[mt][nb][0] + b0, acc[mt][nb][1] + b1);
                *(__half2*)(outbase + (size_t)(r0 + 8) * HDIM + cidx) =
                    __floats2half2_rn(acc[mt][nb][2] + b0, acc[mt][nb][3] + b1);
            }
        }
        return;
    }

    // q/k: stage fp32 acc+bias in smem, then RoPE rotate + fp16 store
    float* st = (float*)smem_dyn;   // 128 rows x 64 cols fp32 = 32 KB
    __syncthreads();                // all warps done with pipeline smem
    #pragma unroll
    for (int mt = 0; mt < 4; ++mt) {
        const int r0 = wm + mt * 16 + (lane >> 2);
        #pragma unroll
        for (int nb = 0; nb < 4; ++nb) {
            const int cidx = wn + nb * 8 + (lane & 3) * 2;
            const float b0 = bias[n0 + cidx], b1 = bias[n0 + cidx + 1];
            st[r0 * 64 + cidx]           = acc[mt][nb][0] + b0;
            st[r0 * 64 + cidx + 1]       = acc[mt][nb][1] + b1;
            st[(r0 + 8) * 64 + cidx]     = acc[mt][nb][2] + b0;
            st[(r0 + 8) * 64 + cidx + 1] = acc[mt][nb][3] + b1;
        }
    }
    __syncthreads();

    const float QS = (sec == 0) ? 0.125f * 1.4426950408889634f : 1.0f;
    #pragma unroll
    for (int i = 0; i < 16; ++i) {
        const int row = i * 8 + (tid >> 4);
        const int d   = (tid & 15) * 2;       // 0,2,...,30
        const float x1a = st[row * 64 + d];
        const float x1b = st[row * 64 + d + 1];
        const float x2a = st[row * 64 + d + 32];
        const float x2b = st[row * 64 + d + 33];

        const float tf = (float)(t0 + row);
        float sa, ca, sb_, cb;
        const float fa = exp2f((float)d       * (-13.2877123795494493f / 32.0f));
        const float fb = exp2f((float)(d + 1) * (-13.2877123795494493f / 32.0f));
        sincosf(tf * fa, &sa, &ca);
        sincosf(tf * fb, &sb_, &cb);

        const float o1a = (x1a * ca - x2a * sa) * QS;
        const float o1b = (x1b * cb - x2b * sb_) * QS;
        const float o2a = (x2a * ca + x1a * sa) * QS;
        const float o2b = (x2b * cb + x1b * sb_) * QS;

        *(__half2*)(outbase + (size_t)row * HDIM + d)      = __floats2half2_rn(o1a, o1b);
        *(__half2*)(outbase + (size_t)row * HDIM + d + 32) = __floats2half2_rn(o2a, o2b);
    }
}

// ---------------------------------------------------------------------------
// GEMM2: fp16 in, fp32 out, 128x128x64, 3-stage, 256 threads. (unchanged)
// ---------------------------------------------------------------------------
#define GM_NSTG 3
#define GM_STG_BYTES 32768   // 16KB A + 16KB B

__global__ __launch_bounds__(256) void hgemm_bias_kernel(
    const __half* __restrict__ A,   // [M][K]
    const __half* __restrict__ Bt,  // [N][K]
    const float* __restrict__ bias, float* __restrict__ C,
    int M, int N, int K)
{
    const int tid = threadIdx.x, lane = tid & 31, wid = tid >> 5;
    const int m0 = blockIdx.y * 128, n0 = blockIdx.x * 128;
    const int wm = (wid >> 2) * 64, wn = (wid & 3) * 32;
    const int lrow = lane & 15, lcol8 = (lane >> 4) * 8;

    const uint32_t sBase = (uint32_t)__cvta_generic_to_shared(smem_dyn);

    const __half* Ag = A  + (size_t)m0 * K;
    const __half* Bg = Bt + (size_t)n0 * K;

    auto loadTile = [&](int it, int stg) {
        const __half* ag = Ag + it * GM_BK;
        const __half* bg = Bg + it * GM_BK;
        const uint32_t sa = sBase + stg * GM_STG_BYTES;
        const uint32_t sb = sa + 16384;
        #pragma unroll
        for (int e = tid; e < 1024; e += 256) {
            const int row = e >> 3, ch = e & 7;
            const uint32_t so = 2 * sw_off(row, ch * 8);
            cp16(sa + so, ag + (size_t)row * K + ch * 8);
            cp16(sb + so, bg + (size_t)row * K + ch * 8);
        }
        asm volatile("cp.async.commit_group;" ::: "memory");
    };

    float acc[4][4][4];
    #pragma unroll
    for (int mt = 0; mt < 4; ++mt)
        #pragma unroll
        for (int nb = 0; nb < 4; ++nb)
            #pragma unroll
            for (int r = 0; r < 4; ++r) acc[mt][nb][r] = 0.f;

    const int kIters = K / GM_BK;
    loadTile(0, 0);
    loadTile(1, 1);

    for (int it = 0; it < kIters; ++it) {
        asm volatile("cp.async.wait_group 1;" ::: "memory");
        __syncthreads();

        if (it + 2 < kIters) loadTile(it + 2, (it + 2) % GM_NSTG);
        else asm volatile("cp.async.commit_group;" ::: "memory");

        const uint32_t sa = sBase + (it % GM_NSTG) * GM_STG_BYTES;
        const uint32_t sb = sa + 16384;

        #pragma unroll
        for (int k16 = 0; k16 < 4; ++k16) {
            uint32_t af[4][4];
            #pragma unroll
            for (int mt = 0; mt < 4; ++mt)
                ldm_x4(af[mt][0], af[mt][1], af[mt][2], af[mt][3],
                       sa + 2 * sw_off(wm + mt * 16 + lrow, k16 * 16 + lcol8));
            uint32_t bfr[4][2];
            #pragma unroll
            for (int nt = 0; nt < 2; ++nt) {
                uint32_t r0, r1, r2, r3;
                ldm_x4(r0, r1, r2, r3,
                       sb + 2 * sw_off(wn + nt * 16 + lrow, k16 * 16 + lcol8));
                bfr[2 * nt][0] = r0; bfr[2 * nt][1] = r2;
                bfr[2 * nt + 1][0] = r1; bfr[2 * nt + 1][1] = r3;
            }
            #pragma unroll
            for (int mt = 0; mt < 4; ++mt)
                #pragma unroll
                for (int nb = 0; nb < 4; ++nb)
                    mma16816_f16(acc[mt][nb], af[mt], bfr[nb][0], bfr[nb][1]);
        }
    }

    #pragma unroll
    for (int mt = 0; mt < 4; ++mt) {
        const int r0 = m0 + wm + mt * 16 + (lane >> 2);
        #pragma unroll
        for (int nb = 0; nb < 4; ++nb) {
            const int cidx = n0 + wn + nb * 8 + (lane & 3) * 2;
            const float b0 = bias[cidx], b1 = bias[cidx + 1];
            *(float2*)(C + (size_t)r0 * N + cidx) =
                make_float2(acc[mt][nb][0] + b0, acc[mt][nb][1] + b1);
            *(float2*)(C + (size_t)(r0 + 8) * N + cidx) =
                make_float2(acc[mt][nb][2] + b0, acc[mt][nb][3] + b1);
        }
    }
}

// ---------------------------------------------------------------------------
// fp16 flash attention (unchanged from R11 best).
// ---------------------------------------------------------------------------
#define FA_BM 128
#define FA_BN 64
#define FA_TILES (SEQ / FA_BN)   // 32

__global__ __launch_bounds__(256) void fa_kernel(
    const __half* __restrict__ Q, const __half* __restrict__ K,
    const __half* __restrict__ V, __half* __restrict__ attn)
{
    const int bh = blockIdx.y;
    const int b  = bh >> 4;
    const int h  = bh & 15;
    const int q0 = blockIdx.x * FA_BM;
    const int tid  = threadIdx.x;
    const int lane = tid & 31;
    const int wid  = tid >> 5;

    __shared__ __half sQ[FA_BM * HDIM];
    __shared__ __half sK[2][FA_BN * HDIM];
    __shared__ __half sV[2][FA_BN * HDIM];

    const __half* qg = Q + ((size_t)bh * SEQ + q0) * HDIM;
    const __half* kg = K + (size_t)bh * SEQ * HDIM;
    const __half* vg = V + (size_t)bh * SEQ * HDIM;

    const uint32_t sQb  = (uint32_t)__cvta_generic_to_shared(sQ);
    const uint32_t sKb0 = (uint32_t)__cvta_generic_to_shared(sK[0]);
    const uint32_t sKb1 = (uint32_t)__cvta_generic_to_shared(sK[1]);
    const uint32_t sVb0 = (uint32_t)__cvta_generic_to_shared(sV[0]);
    const uint32_t sVb1 = (uint32_t)__cvta_generic_to_shared(sV[1]);

    #pragma unroll
    for (int e = tid; e < FA_BM * 8; e += 256) {
        const int row = e >> 3, ch = e & 7;
        *(uint4*)&sQ[sw_off(row, ch * 8)] = *(const uint4*)(qg + row * 64 + ch * 8);
    }

    #pragma unroll
    for (int pt = 0; pt < 2; ++pt) {
        const __half* kt = kg + pt * FA_BN * HDIM;
        const __half* vt = vg + pt * FA_BN * HDIM;
        const uint32_t kb = pt ? sKb1 : sKb0;
        const uint32_t vb = pt ? sVb1 : sVb0;
        #pragma unroll
        for (int e = tid; e < FA_BN * 8; e += 256) {
            const int row = e >> 3, ch = e & 7;
            const uint32_t so = 2 * sw_off(row, ch * 8);
            cp16(kb + so, kt + row * 64 + ch * 8);
            cp16(vb + so, vt + row * 64 + ch * 8);
        }
        asm volatile("cp.async.commit_group;" ::: "memory");
    }

    __syncthreads();

    uint32_t aq[4][4];
    {
        const int qr = wid * 16 + (lane & 15);
        const int qc = (lane >> 4) * 8;
        #pragma unroll
        for (int c4 = 0; c4 < 4; ++c4)
            ldm_x4(aq[c4][0], aq[c4][1], aq[c4][2], aq[c4][3],
                   sQb + 2 * sw_off(qr, c4 * 16 + qc));
    }

    float o[8][4];
    #pragma unroll
    for (int j = 0; j < 8; ++j)
        #pragma unroll
        for (int r = 0; r < 4; ++r) o[j][r] = 0.f;
    float m0 = -1e30f, m1 = -1e30f, l0 = 0.f, l1 = 0.f;

    const int lrow = lane & 15;
    const int lcol8 = (lane >> 4) * 8;

    for (int t = 0; t < FA_TILES; ++t) {
        if (t < FA_TILES - 1)
            asm volatile("cp.async.wait_group 1;" ::: "memory");
        else
            asm volatile("cp.async.wait_group 0;" ::: "memory");
        __syncthreads();

        const uint32_t kb = (t & 1) ? sKb1 : sKb0;
        const uint32_t vb = (t & 1) ? sVb1 : sVb0;

        float c[8][4];
        #pragma unroll
        for (int j = 0; j < 8; ++j)
            #pragma unroll
            for (int r = 0; r < 4; ++r) c[j][r] = 0.f;

        #pragma unroll
        for (int n16 = 0; n16 < 4; ++n16) {
            #pragma unroll
            for (int dc = 0; dc < 4; ++dc) {
                uint32_t r0, r1, r2, r3;
                ldm_x4(r0, r1, r2, r3,
                       kb + 2 * sw_off(n16 * 16 + lrow, dc * 16 + lcol8));
                mma16816_f16(c[2 * n16 + 0], aq[dc], r0, r2);
                mma16816_f16(c[2 * n16 + 1], aq[dc], r1, r3);
            }
        }

        float t0 = -1e30f, t1 = -1e30f;
        #pragma unroll
        for (int j = 0; j < 8; ++j) {
            t0 = fmaxf(t0, fmaxf(c[j][0], c[j][1]));
            t1 = fmaxf(t1, fmaxf(c[j][2], c[j][3]));
        }
        t0 = fmaxf(t0, __shfl_xor_sync(0xffffffffu, t0, 1));
        t0 = fmaxf(t0, __shfl_xor_sync(0xffffffffu, t0, 2));
        t1 = fmaxf(t1, __shfl_xor_sync(0xffffffffu, t1, 1));
        t1 = fmaxf(t1, __shfl_xor_sync(0xffffffffu, t1, 2));

        const float m0n = fmaxf(m0, t0);
        const float m1n = fmaxf(m1, t1);
        const float a0 = ex2f(m0 - m0n);
        const float a1 = ex2f(m1 - m1n);
        m0 = m0n; m1 = m1n;

        #pragma unroll
        for (int j = 0; j < 8; ++j) {
            o[j][0] *= a0; o[j][1] *= a0;
            o[j][2] *= a1; o[j][3] *= a1;
        }

        float s0 = 0.f, s1 = 0.f;
        #pragma unroll
        for (int kc = 0; kc < 4; ++kc) {
            uint32_t ap[4];
            #pragma unroll
            for (int jj = 0; jj < 2; ++jj) {
                const int j = 2 * kc + jj;
                const float p0 = ex2f(c[j][0] - m0);
                const float p1 = ex2f(c[j][1] - m0);
                const float p2 = ex2f(c[j][2] - m1);
                const float p3 = ex2f(c[j][3] - m1);
                s0 += p0 + p1;
                s1 += p2 + p3;
                __half2 u = __floats2half2_rn(p0, p1);
                __half2 w = __floats2half2_rn(p2, p3);
                ap[2 * jj + 0] = *(uint32_t*)&u;
                ap[2 * jj + 1] = *(uint32_t*)&w;
            }
            #pragma unroll
            for (int dc = 0; dc < 4; ++dc) {
                uint32_t r0, r1, r2, r3;
                ldm_x4_t(r0, r1, r2, r3,
                         vb + 2 * sw_off(kc * 16 + lrow, dc * 16 + lcol8));
                mma16816_f16(o[2 * dc + 0], ap, r0, r1);
                mma16816_f16(o[2 * dc + 1], ap, r2, r3);
            }
        }

        s0 += __shfl_xor_sync(0xffffffffu, s0, 1);
        s0 += __shfl_xor_sync(0xffffffffu, s0, 2);
        s1 += __shfl_xor_sync(0xffffffffu, s1, 1);
        s1 += __shfl_xor_sync(0xffffffffu, s1, 2);
        l0 = l0 * a0 + s0;
        l1 = l1 * a1 + s1;

        __syncthreads();

        if (t + 2 < FA_TILES) {
            const __half* kt = kg + (t + 2) * FA_BN * HDIM;
            const __half* vt = vg + (t + 2) * FA_BN * HDIM;
            const uint32_t kbn = (t & 1) ? sKb1 : sKb0;
            const uint32_t vbn = (t & 1) ? sVb1 : sVb0;
            #pragma unroll
            for (int e = tid; e < FA_BN * 8; e += 256) {
                const int row = e >> 3, ch = e & 7;
                const uint32_t so = 2 * sw_off(row, ch * 8);
                cp16(kbn + so, kt + row * 64 + ch * 8);
                cp16(vbn + so, vt + row * 64 + ch * 8);
            }
        }
        asm volatile("cp.async.commit_group;" ::: "memory");
    }

    const float inv0 = 1.0f / l0;
    const float inv1 = 1.0f / l1;
    const int g = lane >> 2;
    const int cq = (lane & 3) * 2;
    const int row0 = q0 + wid * 16 + g;
    const int row1 = row0 + 8;
    __half* ab0 = attn + (size_t)(b * SEQ + row0) * CDIM + h * HDIM + cq;
    __half* ab1 = attn + (size_t)(b * SEQ + row1) * CDIM + h * HDIM + cq;
    #pragma unroll
    for (int j = 0; j < 8; ++j) {
        *(__half2*)(ab0 + j * 8) = __floats2half2_rn(o[j][0] * inv0, o[j][1] * inv0);
        *(__half2*)(ab1 + j * 8) = __floats2half2_rn(o[j][2] * inv1, o[j][3] * inv1);
    }
}

// ---------------------------------------------------------------------------
// Launch
// ---------------------------------------------------------------------------
extern "C" void kernel_launch(void* const* d_in, const int* in_sizes, int n_in,
                              void* d_out, int out_size)
{
    const float* x    = (const float*)d_in[0];
    const float* Wqkv = (const float*)d_in[1];
    const float* bqkv = (const float*)d_in[2];
    const float* Wout = (const float*)d_in[3];
    const float* bout = (const float*)d_in[4];
    float* out = (float*)d_out;

    __half *x16 = nullptr, *qb = nullptr, *kb = nullptr, *vb = nullptr;
    __half *attn = nullptr, *W1 = nullptr, *W2 = nullptr;
    cudaGetSymbolAddress((void**)&x16, g_x16);
    cudaGetSymbolAddress((void**)&qb, g_qb);
    cudaGetSymbolAddress((void**)&kb, g_kb);
    cudaGetSymbolAddress((void**)&vb, g_vb);
    cudaGetSymbolAddress((void**)&attn, g_attn);
    cudaGetSymbolAddress((void**)&W1,  g_W1);
    cudaGetSymbolAddress((void**)&W2,  g_W2);

    const int G1_SMEM = G1_NSTG * G1_STG_BYTES;     // 73728
    const int G2_SMEM = GM_NSTG * GM_STG_BYTES;     // 98304
    cudaFuncSetAttribute(hgemm_rope_kernel,
                         cudaFuncAttributeMaxDynamicSharedMemorySize, G1_SMEM);
    cudaFuncSetAttribute(hgemm_bias_kernel,
                         cudaFuncAttributeMaxDynamicSharedMemorySize, G2_SMEM);

    // 1) fused prep: cast x -> x16, transpose Wqkv -> W1, Wout -> W2
    prep_kernel<<<PREP_CAST_BLKS + PREP_W1_BLKS + PREP_W2_BLKS, 256>>>(
        x, x16, Wqkv, W1, Wout, W2);

    // 2) qkv GEMM + fused RoPE + relayout -> qb/kb/vb directly
    hgemm_rope_kernel<<<dim3(QKVC / 64, MROWS / 128), 128, G1_SMEM>>>(
        x16, W1, bqkv, qb, kb, vb, MROWS, QKVC, CDIM);

    // 3) flash attention -> attn fp16
    fa_kernel<<<dim3(SEQ / FA_BM, BATCH * NHEAD), 256>>>(qb, kb, vb, attn);

    // 4) out = attn @ Wout + bout
    hgemm_bias_kernel<<<dim3(CDIM / 128, MROWS / 128), 256, G2_SMEM>>>(
        attn, W2, bout, out, MROWS, CDIM, CDIM);
}

// round 14
// speedup vs baseline: 1.1398x; 1.0374x over previous
#include <cuda_runtime.h>
#include <cuda_fp16.h>
#include <cstdint>
#include <cstddef>

// Problem constants (fixed shapes from setup_inputs)
#define BATCH 2
#define SEQ   2048
#define CDIM  1024
#define NHEAD 16
#define HDIM  64
#define MROWS (BATCH * SEQ)          // 4096
#define QKVC  (3 * CDIM)             // 3072

// Scratch (allocation-free rule: __device__ globals)
__device__ __half g_x16[(size_t)MROWS * CDIM];       //  8 MB fp16 cast of x
__device__ __half g_qb[(size_t)MROWS * CDIM];        //  8 MB [b][h][t][d]
__device__ __half g_kb[(size_t)MROWS * CDIM];
__device__ __half g_vb[(size_t)MROWS * CDIM];
__device__ __half g_attn[(size_t)MROWS * CDIM];      //  8 MB attn output fp16
__device__ __half g_W1 [(size_t)QKVC * CDIM];        //  6 MB [N=3072][K=1024] Wqkv^T fp16
__device__ __half g_W2 [(size_t)CDIM * CDIM];        //  2 MB [N=1024][K=1024] Wout^T fp16

// ---------------------------------------------------------------------------
// Common PTX helpers
// ---------------------------------------------------------------------------
__device__ __forceinline__ uint32_t sw_off(int row, int col) {
    // XOR swizzle on 16B chunks within a 64-elt (128B) 16-bit row
    return (uint32_t)(row * 64 + ((((col >> 3) ^ (row & 7)) << 3) | (col & 7)));
}
__device__ __forceinline__ void ldm_x4(uint32_t& r0, uint32_t& r1,
                                       uint32_t& r2, uint32_t& r3, uint32_t a) {
    asm volatile("ldmatrix.sync.aligned.m8n8.x4.shared.b16 {%0,%1,%2,%3}, [%4];"
                 : "=r"(r0), "=r"(r1), "=r"(r2), "=r"(r3) : "r"(a));
}
__device__ __forceinline__ void ldm_x4_t(uint32_t& r0, uint32_t& r1,
                                         uint32_t& r2, uint32_t& r3, uint32_t a) {
    asm volatile("ldmatrix.sync.aligned.m8n8.x4.trans.shared.b16 {%0,%1,%2,%3}, [%4];"
                 : "=r"(r0), "=r"(r1), "=r"(r2), "=r"(r3) : "r"(a));
}
__device__ __forceinline__ void mma16816_f16(float* c, const uint32_t* a,
                                             uint32_t b0, uint32_t b1) {
    asm volatile(
        "mma.sync.aligned.m16n8k16.row.col.f32.f16.f16.f32 "
        "{%0,%1,%2,%3}, {%4,%5,%6,%7}, {%8,%9}, {%0,%1,%2,%3};"
        : "+f"(c[0]), "+f"(c[1]), "+f"(c[2]), "+f"(c[3])
        : "r"(a[0]), "r"(a[1]), "r"(a[2]), "r"(a[3]), "r"(b0), "r"(b1));
}
__device__ __forceinline__ float ex2f(float x) {
    float r;
    asm("ex2.approx.ftz.f32 %0, %1;" : "=f"(r) : "f"(x));
    return r;
}
__device__ __forceinline__ void cp16(uint32_t dst, const void* src) {
    asm volatile("cp.async.cg.shared.global [%0], [%1], 16;" :: "r"(dst), "l"(src));
}

// ---------------------------------------------------------------------------
// Fused prep: (a) x -> fp16 cast, (b) Wqkv transpose+cast, (c) Wout
// transpose+cast. 256 threads flat.
// ---------------------------------------------------------------------------
__device__ __forceinline__ void trans_tile(const float* __restrict__ W,
                                           __half* __restrict__ Wt,
                                           int K, int N, int bx, int by,
                                           int tx, int ty, float (*s)[33])
{
    const int k0 = by * 32, n0 = bx * 32;
    #pragma unroll
    for (int i = 0; i < 4; ++i)
        s[ty + i * 8][tx] = W[(size_t)(k0 + ty + i * 8) * N + n0 + tx];
    __syncthreads();
    #pragma unroll
    for (int i = 0; i < 4; ++i) {
        const int n = n0 + ty + i * 8, k = k0 + tx;
        Wt[(size_t)n * K + k] = __float2half_rn(s[tx][ty + i * 8]);
    }
}

#define PREP_CAST_BLKS  (MROWS * CDIM / 2 / 256)          // 8192
#define PREP_W1_BLKS    ((QKVC / 32) * (CDIM / 32))       // 3072
#define PREP_W2_BLKS    ((CDIM / 32) * (CDIM / 32))       // 1024

__global__ void prep_kernel(const float* __restrict__ x, __half* __restrict__ x16,
                            const float* __restrict__ Wqkv, __half* __restrict__ W1,
                            const float* __restrict__ Wout, __half* __restrict__ W2)
{
    __shared__ float s[32][33];
    const int bid = blockIdx.x;
    const int tid = threadIdx.x;
    if (bid < PREP_CAST_BLKS) {
        const int idx = bid * 256 + tid;
        const float2 v = *(const float2*)(x + (size_t)idx * 2);
        __half2 hh;
        hh.x = __float2half_rn(v.x);
        hh.y = __float2half_rn(v.y);
        *(__half2*)(x16 + (size_t)idx * 2) = hh;
    } else if (bid < PREP_CAST_BLKS + PREP_W1_BLKS) {
        const int j = bid - PREP_CAST_BLKS;
        trans_tile(Wqkv, W1, CDIM, QKVC, j % (QKVC / 32), j / (QKVC / 32),
                   tid & 31, tid >> 5, s);
    } else {
        const int j = bid - PREP_CAST_BLKS - PREP_W1_BLKS;
        trans_tile(Wout, W2, CDIM, CDIM, j % (CDIM / 32), j / (CDIM / 32),
                   tid & 31, tid >> 5, s);
    }
}

// ---------------------------------------------------------------------------
// GEMM1 + fused RoPE epilogue (unchanged from R13).
// ---------------------------------------------------------------------------
#define GM_BK 64
#define G1_NSTG 3
#define G1_STG_BYTES 24576   // 16 KB A + 8 KB B

extern __shared__ __half smem_dyn[];

__global__ __launch_bounds__(128, 3) void hgemm_rope_kernel(
    const __half* __restrict__ A,   // [M][K] = x16
    const __half* __restrict__ Bt,  // [N][K] = W1
    const float* __restrict__ bias, // bqkv
    __half* __restrict__ qb, __half* __restrict__ kb, __half* __restrict__ vb,
    int M, int N, int K)
{
    const int tid = threadIdx.x, lane = tid & 31, wid = tid >> 5;
    const int m0 = blockIdx.y * 128, n0 = blockIdx.x * 64;
    const int wm = (wid >> 1) * 64, wn = (wid & 1) * 32;
    const int lrow = lane & 15, lcol8 = (lane >> 4) * 8;

    const uint32_t sBase = (uint32_t)__cvta_generic_to_shared(smem_dyn);

    const __half* Ag = A  + (size_t)m0 * K;
    const __half* Bg = Bt + (size_t)n0 * K;

    auto loadTile = [&](int it, int stg) {
        const __half* ag = Ag + it * GM_BK;
        const __half* bg = Bg + it * GM_BK;
        const uint32_t sa = sBase + stg * G1_STG_BYTES;
        const uint32_t sb = sa + 16384;
        #pragma unroll
        for (int e = tid; e < 1024; e += 128) {
            const int row = e >> 3, ch = e & 7;
            cp16(sa + 2 * sw_off(row, ch * 8), ag + (size_t)row * K + ch * 8);
        }
        #pragma unroll
        for (int e = tid; e < 512; e += 128) {
            const int row = e >> 3, ch = e & 7;
            cp16(sb + 2 * sw_off(row, ch * 8), bg + (size_t)row * K + ch * 8);
        }
        asm volatile("cp.async.commit_group;" ::: "memory");
    };

    float acc[4][4][4];
    #pragma unroll
    for (int mt = 0; mt < 4; ++mt)
        #pragma unroll
        for (int nb = 0; nb < 4; ++nb)
            #pragma unroll
            for (int r = 0; r < 4; ++r) acc[mt][nb][r] = 0.f;

    const int kIters = K / GM_BK;
    loadTile(0, 0);
    loadTile(1, 1);

    uint32_t af[2][4][4];
    uint32_t bf[2][4][2];

    for (int it = 0; it < kIters; ++it) {
        asm volatile("cp.async.wait_group 1;" ::: "memory");
        __syncthreads();

        if (it + 2 < kIters) loadTile(it + 2, (it + 2) % G1_NSTG);
        else asm volatile("cp.async.commit_group;" ::: "memory");

        const uint32_t sa = sBase + (it % G1_NSTG) * G1_STG_BYTES;
        const uint32_t sb = sa + 16384;

        #pragma unroll
        for (int mt = 0; mt < 4; ++mt)
            ldm_x4(af[0][mt][0], af[0][mt][1], af[0][mt][2], af[0][mt][3],
                   sa + 2 * sw_off(wm + mt * 16 + lrow, lcol8));
        #pragma unroll
        for (int nt = 0; nt < 2; ++nt) {
            uint32_t r0, r1, r2, r3;
            ldm_x4(r0, r1, r2, r3, sb + 2 * sw_off(wn + nt * 16 + lrow, lcol8));
            bf[0][2 * nt][0] = r0;     bf[0][2 * nt][1] = r2;
            bf[0][2 * nt + 1][0] = r1; bf[0][2 * nt + 1][1] = r3;
        }

        #pragma unroll
        for (int k16 = 0; k16 < 4; ++k16) {
            const int cur = k16 & 1, nxt = cur ^ 1;
            if (k16 < 3) {
                #pragma unroll
                for (int mt = 0; mt < 4; ++mt)
                    ldm_x4(af[nxt][mt][0], af[nxt][mt][1],
                           af[nxt][mt][2], af[nxt][mt][3],
                           sa + 2 * sw_off(wm + mt * 16 + lrow,
                                           (k16 + 1) * 16 + lcol8));
                #pragma unroll
                for (int nt = 0; nt < 2; ++nt) {
                    uint32_t r0, r1, r2, r3;
                    ldm_x4(r0, r1, r2, r3,
                           sb + 2 * sw_off(wn + nt * 16 + lrow,
                                           (k16 + 1) * 16 + lcol8));
                    bf[nxt][2 * nt][0] = r0;     bf[nxt][2 * nt][1] = r2;
                    bf[nxt][2 * nt + 1][0] = r1; bf[nxt][2 * nt + 1][1] = r3;
                }
            }
            #pragma unroll
            for (int mt = 0; mt < 4; ++mt)
                #pragma unroll
                for (int nb = 0; nb < 4; ++nb)
                    mma16816_f16(acc[mt][nb], af[cur][mt],
                                 bf[cur][nb][0], bf[cur][nb][1]);
        }
    }

    // ---- fused epilogue ----
    const int sec = n0 >> 10;               // 0=q, 1=k, 2=v
    const int h   = (n0 & 1023) >> 6;
    const int b   = m0 >> 11;
    const int t0  = m0 & (SEQ - 1);
    __half* outbase = (sec == 0 ? qb : (sec == 1 ? kb : vb))
                      + ((size_t)(b * NHEAD + h) * SEQ + t0) * HDIM;

    if (sec == 2) {
        #pragma unroll
        for (int mt = 0; mt < 4; ++mt) {
            const int r0 = wm + mt * 16 + (lane >> 2);
            #pragma unroll
            for (int nb = 0; nb < 4; ++nb) {
                const int cidx = wn + nb * 8 + (lane & 3) * 2;
                const float b0 = bias[n0 + cidx], b1 = bias[n0 + cidx + 1];
                *(__half2*)(outbase + (size_t)r0 * HDIM + cidx) =
                    __floats2half2_rn(acc[mt][nb][0] + b0, acc[mt][nb][1] + b1);
                *(__half2*)(outbase + (size_t)(r0 + 8) * HDIM + cidx) =
                    __floats2half2_rn(acc[mt][nb][2] + b0, acc[mt][nb][3] + b1);
            }
        }
        return;
    }

    float* st = (float*)smem_dyn;   // 128 x 64 fp32 = 32 KB
    __syncthreads();
    #pragma unroll
    for (int mt = 0; mt < 4; ++mt) {
        const int r0 = wm + mt * 16 + (lane >> 2);
        #pragma unroll
        for (int nb = 0; nb < 4; ++nb) {
            const int cidx = wn + nb * 8 + (lane & 3) * 2;
            const float b0 = bias[n0 + cidx], b1 = bias[n0 + cidx + 1];
            st[r0 * 64 + cidx]           = acc[mt][nb][0] + b0;
            st[r0 * 64 + cidx + 1]       = acc[mt][nb][1] + b1;
            st[(r0 + 8) * 64 + cidx]     = acc[mt][nb][2] + b0;
            st[(r0 + 8) * 64 + cidx + 1] = acc[mt][nb][3] + b1;
        }
    }
    __syncthreads();

    const float QS = (sec == 0) ? 0.125f * 1.4426950408889634f : 1.0f;
    #pragma unroll
    for (int i = 0; i < 16; ++i) {
        const int row = i * 8 + (tid >> 4);
        const int d   = (tid & 15) * 2;
        const float x1a = st[row * 64 + d];
        const float x1b = st[row * 64 + d + 1];
        const float x2a = st[row * 64 + d + 32];
        const float x2b = st[row * 64 + d + 33];

        const float tf = (float)(t0 + row);
        float sa, ca, sb_, cb;
        const float fa = exp2f((float)d       * (-13.2877123795494493f / 32.0f));
        const float fb = exp2f((float)(d + 1) * (-13.2877123795494493f / 32.0f));
        sincosf(tf * fa, &sa, &ca);
        sincosf(tf * fb, &sb_, &cb);

        const float o1a = (x1a * ca - x2a * sa) * QS;
        const float o1b = (x1b * cb - x2b * sb_) * QS;
        const float o2a = (x2a * ca + x1a * sa) * QS;
        const float o2b = (x2b * cb + x1b * sb_) * QS;

        *(__half2*)(outbase + (size_t)row * HDIM + d)      = __floats2half2_rn(o1a, o1b);
        *(__half2*)(outbase + (size_t)row * HDIM + d + 32) = __floats2half2_rn(o2a, o2b);
    }
}

// ---------------------------------------------------------------------------
// GEMM2: fp16 in, fp32 out, 128x128x64, 3-stage, 256 threads. (unchanged)
// ---------------------------------------------------------------------------
#define GM_NSTG 3
#define GM_STG_BYTES 32768   // 16KB A + 16KB B

__global__ __launch_bounds__(256) void hgemm_bias_kernel(
    const __half* __restrict__ A,   // [M][K]
    const __half* __restrict__ Bt,  // [N][K]
    const float* __restrict__ bias, float* __restrict__ C,
    int M, int N, int K)
{
    const int tid = threadIdx.x, lane = tid & 31, wid = tid >> 5;
    const int m0 = blockIdx.y * 128, n0 = blockIdx.x * 128;
    const int wm = (wid >> 2) * 64, wn = (wid & 3) * 32;
    const int lrow = lane & 15, lcol8 = (lane >> 4) * 8;

    const uint32_t sBase = (uint32_t)__cvta_generic_to_shared(smem_dyn);

    const __half* Ag = A  + (size_t)m0 * K;
    const __half* Bg = Bt + (size_t)n0 * K;

    auto loadTile = [&](int it, int stg) {
        const __half* ag = Ag + it * GM_BK;
        const __half* bg = Bg + it * GM_BK;
        const uint32_t sa = sBase + stg * GM_STG_BYTES;
        const uint32_t sb = sa + 16384;
        #pragma unroll
        for (int e = tid; e < 1024; e += 256) {
            const int row = e >> 3, ch = e & 7;
            const uint32_t so = 2 * sw_off(row, ch * 8);
            cp16(sa + so, ag + (size_t)row * K + ch * 8);
            cp16(sb + so, bg + (size_t)row * K + ch * 8);
        }
        asm volatile("cp.async.commit_group;" ::: "memory");
    };

    float acc[4][4][4];
    #pragma unroll
    for (int mt = 0; mt < 4; ++mt)
        #pragma unroll
        for (int nb = 0; nb < 4; ++nb)
            #pragma unroll
            for (int r = 0; r < 4; ++r) acc[mt][nb][r] = 0.f;

    const int kIters = K / GM_BK;
    loadTile(0, 0);
    loadTile(1, 1);

    for (int it = 0; it < kIters; ++it) {
        asm volatile("cp.async.wait_group 1;" ::: "memory");
        __syncthreads();

        if (it + 2 < kIters) loadTile(it + 2, (it + 2) % GM_NSTG);
        else asm volatile("cp.async.commit_group;" ::: "memory");

        const uint32_t sa = sBase + (it % GM_NSTG) * GM_STG_BYTES;
        const uint32_t sb = sa + 16384;

        #pragma unroll
        for (int k16 = 0; k16 < 4; ++k16) {
            uint32_t af[4][4];
            #pragma unroll
            for (int mt = 0; mt < 4; ++mt)
                ldm_x4(af[mt][0], af[mt][1], af[mt][2], af[mt][3],
                       sa + 2 * sw_off(wm + mt * 16 + lrow, k16 * 16 + lcol8));
            uint32_t bfr[4][2];
            #pragma unroll
            for (int nt = 0; nt < 2; ++nt) {
                uint32_t r0, r1, r2, r3;
                ldm_x4(r0, r1, r2, r3,
                       sb + 2 * sw_off(wn + nt * 16 + lrow, k16 * 16 + lcol8));
                bfr[2 * nt][0] = r0; bfr[2 * nt][1] = r2;
                bfr[2 * nt + 1][0] = r1; bfr[2 * nt + 1][1] = r3;
            }
            #pragma unroll
            for (int mt = 0; mt < 4; ++mt)
                #pragma unroll
                for (int nb = 0; nb < 4; ++nb)
                    mma16816_f16(acc[mt][nb], af[mt], bfr[nb][0], bfr[nb][1]);
        }
    }

    #pragma unroll
    for (int mt = 0; mt < 4; ++mt) {
        const int r0 = m0 + wm + mt * 16 + (lane >> 2);
        #pragma unroll
        for (int nb = 0; nb < 4; ++nb) {
            const int cidx = n0 + wn + nb * 8 + (lane & 3) * 2;
            const float b0 = bias[cidx], b1 = bias[cidx + 1];
            *(float2*)(C + (size_t)r0 * N + cidx) =
                make_float2(acc[mt][nb][0] + b0, acc[mt][nb][1] + b1);
            *(float2*)(C + (size_t)(r0 + 8) * N + cidx) =
                make_float2(acc[mt][nb][2] + b0, acc[mt][nb][3] + b1);
        }
    }
}

// ---------------------------------------------------------------------------
// fp16 flash attention — FA_BM=64, 128 threads (4 warps x 16 q-rows),
// __launch_bounds__(128,4) => 4 CTAs/SM to kill wave-quantization bubble.
// Per-warp math identical to R13 (bit-identical output).
// ---------------------------------------------------------------------------
#define FA_BM 64
#define FA_BN 64
#define FA_TILES (SEQ / FA_BN)   // 32

__global__ __launch_bounds__(128, 4) void fa_kernel(
    const __half* __restrict__ Q, const __half* __restrict__ K,
    const __half* __restrict__ V, __half* __restrict__ attn)
{
    const int bh = blockIdx.y;
    const int b  = bh >> 4;
    const int h  = bh & 15;
    const int q0 = blockIdx.x * FA_BM;
    const int tid  = threadIdx.x;
    const int lane = tid & 31;
    const int wid  = tid >> 5;

    __shared__ __half sQ[FA_BM * HDIM];           // 8 KB
    __shared__ __half sK[2][FA_BN * HDIM];        // 16 KB
    __shared__ __half sV[2][FA_BN * HDIM];        // 16 KB

    const __half* qg = Q + ((size_t)bh * SEQ + q0) * HDIM;
    const __half* kg = K + (size_t)bh * SEQ * HDIM;
    const __half* vg = V + (size_t)bh * SEQ * HDIM;

    const uint32_t sQb  = (uint32_t)__cvta_generic_to_shared(sQ);
    const uint32_t sKb0 = (uint32_t)__cvta_generic_to_shared(sK[0]);
    const uint32_t sKb1 = (uint32_t)__cvta_generic_to_shared(sK[1]);
    const uint32_t sVb0 = (uint32_t)__cvta_generic_to_shared(sV[0]);
    const uint32_t sVb1 = (uint32_t)__cvta_generic_to_shared(sV[1]);

    #pragma unroll
    for (int e = tid; e < FA_BM * 8; e += 128) {
        const int row = e >> 3, ch = e & 7;
        *(uint4*)&sQ[sw_off(row, ch * 8)] = *(const uint4*)(qg + row * 64 + ch * 8);
    }

    #pragma unroll
    for (int pt = 0; pt < 2; ++pt) {
        const __half* kt = kg + pt * FA_BN * HDIM;
        const __half* vt = vg + pt * FA_BN * HDIM;
        const uint32_t kb = pt ? sKb1 : sKb0;
        const uint32_t vb = pt ? sVb1 : sVb0;
        #pragma unroll
        for (int e = tid; e < FA_BN * 8; e += 128) {
            const int row = e >> 3, ch = e & 7;
            const uint32_t so = 2 * sw_off(row, ch * 8);
            cp16(kb + so, kt + row * 64 + ch * 8);
            cp16(vb + so, vt + row * 64 + ch * 8);
        }
        asm volatile("cp.async.commit_group;" ::: "memory");
    }

    __syncthreads();

    uint32_t aq[4][4];
    {
        const int qr = wid * 16 + (lane & 15);
        const int qc = (lane >> 4) * 8;
        #pragma unroll
        for (int c4 = 0; c4 < 4; ++c4)
            ldm_x4(aq[c4][0], aq[c4][1], aq[c4][2], aq[c4][3],
                   sQb + 2 * sw_off(qr, c4 * 16 + qc));
    }

    float o[8][4];
    #pragma unroll
    for (int j = 0; j < 8; ++j)
        #pragma unroll
        for (int r = 0; r < 4; ++r) o[j][r] = 0.f;
    float m0 = -1e30f, m1 = -1e30f, l0 = 0.f, l1 = 0.f;

    const int lrow = lane & 15;
    const int lcol8 = (lane >> 4) * 8;

    for (int t = 0; t < FA_TILES; ++t) {
        if (t < FA_TILES - 1)
            asm volatile("cp.async.wait_group 1;" ::: "memory");
        else
            asm volatile("cp.async.wait_group 0;" ::: "memory");
        __syncthreads();

        const uint32_t kb = (t & 1) ? sKb1 : sKb0;
        const uint32_t vb = (t & 1) ? sVb1 : sVb0;

        float c[8][4];
        #pragma unroll
        for (int j = 0; j < 8; ++j)
            #pragma unroll
            for (int r = 0; r < 4; ++r) c[j][r] = 0.f;

        #pragma unroll
        for (int n16 = 0; n16 < 4; ++n16) {
            #pragma unroll
            for (int dc = 0; dc < 4; ++dc) {
                uint32_t r0, r1, r2, r3;
                ldm_x4(r0, r1, r2, r3,
                       kb + 2 * sw_off(n16 * 16 + lrow, dc * 16 + lcol8));
                mma16816_f16(c[2 * n16 + 0], aq[dc], r0, r2);
                mma16816_f16(c[2 * n16 + 1], aq[dc], r1, r3);
            }
        }

        float t0 = -1e30f, t1 = -1e30f;
        #pragma unroll
        for (int j = 0; j < 8; ++j) {
            t0 = fmaxf(t0, fmaxf(c[j][0], c[j][1]));
            t1 = fmaxf(t1, fmaxf(c[j][2], c[j][3]));
        }
        t0 = fmaxf(t0, __shfl_xor_sync(0xffffffffu, t0, 1));
        t0 = fmaxf(t0, __shfl_xor_sync(0xffffffffu, t0, 2));
        t1 = fmaxf(t1, __shfl_xor_sync(0xffffffffu, t1, 1));
        t1 = fmaxf(t1, __shfl_xor_sync(0xffffffffu, t1, 2));

        const float m0n = fmaxf(m0, t0);
        const float m1n = fmaxf(m1, t1);
        const float a0 = ex2f(m0 - m0n);
        const float a1 = ex2f(m1 - m1n);
        m0 = m0n; m1 = m1n;

        #pragma unroll
        for (int j = 0; j < 8; ++j) {
            o[j][0] *= a0; o[j][1] *= a0;
            o[j][2] *= a1; o[j][3] *= a1;
        }

        float s0 = 0.f, s1 = 0.f;
        #pragma unroll
        for (int kc = 0; kc < 4; ++kc) {
            uint32_t ap[4];
            #pragma unroll
            for (int jj = 0; jj < 2; ++jj) {
                const int j = 2 * kc + jj;
                const float p0 = ex2f(c[j][0] - m0);
                const float p1 = ex2f(c[j][1] - m0);
                const float p2 = ex2f(c[j][2] - m1);
                const float p3 = ex2f(c[j][3] - m1);
                s0 += p0 + p1;
                s1 += p2 + p3;
                __half2 u = __floats2half2_rn(p0, p1);
                __half2 w = __floats2half2_rn(p2, p3);
                ap[2 * jj + 0] = *(uint32_t*)&u;
                ap[2 * jj + 1] = *(uint32_t*)&w;
            }
            #pragma unroll
            for (int dc = 0; dc < 4; ++dc) {
                uint32_t r0, r1, r2, r3;
                ldm_x4_t(r0, r1, r2, r3,
                         vb + 2 * sw_off(kc * 16 + lrow, dc * 16 + lcol8));
                mma16816_f16(o[2 * dc + 0], ap, r0, r1);
                mma16816_f16(o[2 * dc + 1], ap, r2, r3);
            }
        }

        s0 += __shfl_xor_sync(0xffffffffu, s0, 1);
        s0 += __shfl_xor_sync(0xffffffffu, s0, 2);
        s1 += __shfl_xor_sync(0xffffffffu, s1, 1);
        s1 += __shfl_xor_sync(0xffffffffu, s1, 2);
        l0 = l0 * a0 + s0;
        l1 = l1 * a1 + s1;

        __syncthreads();

        if (t + 2 < FA_TILES) {
            const __half* kt = kg + (t + 2) * FA_BN * HDIM;
            const __half* vt = vg + (t + 2) * FA_BN * HDIM;
            const uint32_t kbn = (t & 1) ? sKb1 : sKb0;
            const uint32_t vbn = (t & 1) ? sVb1 : sVb0;
            #pragma unroll
            for (int e = tid; e < FA_BN * 8; e += 128) {
                const int row = e >> 3, ch = e & 7;
                const uint32_t so = 2 * sw_off(row, ch * 8);
                cp16(kbn + so, kt + row * 64 + ch * 8);
                cp16(vbn + so, vt + row * 64 + ch * 8);
            }
        }
        asm volatile("cp.async.commit_group;" ::: "memory");
    }

    const float inv0 = 1.0f / l0;
    const float inv1 = 1.0f / l1;
    const int g = lane >> 2;
    const int cq = (lane & 3) * 2;
    const int row0 = q0 + wid * 16 + g;
    const int row1 = row0 + 8;
    __half* ab0 = attn + (size_t)(b * SEQ + row0) * CDIM + h * HDIM + cq;
    __half* ab1 = attn + (size_t)(b * SEQ + row1) * CDIM + h * HDIM + cq;
    #pragma unroll
    for (int j = 0; j < 8; ++j) {
        *(__half2*)(ab0 + j * 8) = __floats2half2_rn(o[j][0] * inv0, o[j][1] * inv0);
        *(__half2*)(ab1 + j * 8) = __floats2half2_rn(o[j][2] * inv1, o[j][3] * inv1);
    }
}

// ---------------------------------------------------------------------------
// Launch
// ---------------------------------------------------------------------------
extern "C" void kernel_launch(void* const* d_in, const int* in_sizes, int n_in,
                              void* d_out, int out_size)
{
    const float* x    = (const float*)d_in[0];
    const float* Wqkv = (const float*)d_in[1];
    const float* bqkv = (const float*)d_in[2];
    const float* Wout = (const float*)d_in[3];
    const float* bout = (const float*)d_in[4];
    float* out = (float*)d_out;

    __half *x16 = nullptr, *qb = nullptr, *kb = nullptr, *vb = nullptr;
    __half *attn = nullptr, *W1 = nullptr, *W2 = nullptr;
    cudaGetSymbolAddress((void**)&x16, g_x16);
    cudaGetSymbolAddress((void**)&qb, g_qb);
    cudaGetSymbolAddress((void**)&kb, g_kb);
    cudaGetSymbolAddress((void**)&vb, g_vb);
    cudaGetSymbolAddress((void**)&attn, g_attn);
    cudaGetSymbolAddress((void**)&W1,  g_W1);
    cudaGetSymbolAddress((void**)&W2,  g_W2);

    const int G1_SMEM = G1_NSTG * G1_STG_BYTES;     // 73728
    const int G2_SMEM = GM_NSTG * GM_STG_BYTES;     // 98304
    cudaFuncSetAttribute(hgemm_rope_kernel,
                         cudaFuncAttributeMaxDynamicSharedMemorySize, G1_SMEM);
    cudaFuncSetAttribute(hgemm_bias_kernel,
                         cudaFuncAttributeMaxDynamicSharedMemorySize, G2_SMEM);

    // 1) fused prep: cast x -> x16, transpose Wqkv -> W1, Wout -> W2
    prep_kernel<<<PREP_CAST_BLKS + PREP_W1_BLKS + PREP_W2_BLKS, 256>>>(
        x, x16, Wqkv, W1, Wout, W2);

    // 2) qkv GEMM + fused RoPE + relayout -> qb/kb/vb directly
    hgemm_rope_kernel<<<dim3(QKVC / 64, MROWS / 128), 128, G1_SMEM>>>(
        x16, W1, bqkv, qb, kb, vb, MROWS, QKVC, CDIM);

    // 3) flash attention -> attn fp16 (finer CTAs, 4/SM residency)
    fa_kernel<<<dim3(SEQ / FA_BM, BATCH * NHEAD), 128>>>(qb, kb, vb, attn);

    // 4) out = attn @ Wout + bout
    hgemm_bias_kernel<<<dim3(CDIM / 128, MROWS / 128), 256, G2_SMEM>>>(
        attn, W2, bout, out, MROWS, CDIM, CDIM);
}